// round 17
// baseline (speedup 1.0000x reference)
#include <cuda_runtime.h>
#include <cuda_bf16.h>
#include <math.h>

// Problem dims
#define BB 1024
#define TT 512
#define FF 64
#define HH 128
#define GG 384   // 3*H, gate order (r, z, n)

__device__ __forceinline__ float sigmoid_fast(float x) {
    return __fdividef(1.f, 1.f + __expf(-x));
}
__device__ __forceinline__ float tanh_fast(float x) {
    return 1.f - __fdividef(2.f, __expf(2.f * x) + 1.f);
}

// cp.async helpers (16B)
__device__ __forceinline__ void cp_async16(unsigned int smem_addr, const void* gptr) {
    asm volatile("cp.async.cg.shared.global [%0], [%1], 16;" :: "r"(smem_addr), "l"(gptr));
}
__device__ __forceinline__ void cp_commit() {
    asm volatile("cp.async.commit_group;");
}
__device__ __forceinline__ void cp_wait_all() {
    asm volatile("cp.async.wait_group 0;" ::: "memory");
}

// bf16 mma m16n8k16 row.col, f32 accumulate
__device__ __forceinline__ void mma_bf16(float* c, const unsigned* a, const unsigned* b) {
    asm volatile(
        "mma.sync.aligned.m16n8k16.row.col.f32.bf16.bf16.f32 "
        "{%0,%1,%2,%3}, {%4,%5,%6,%7}, {%8,%9}, {%0,%1,%2,%3};"
        : "+f"(c[0]), "+f"(c[1]), "+f"(c[2]), "+f"(c[3])
        : "r"(a[0]), "r"(a[1]), "r"(a[2]), "r"(a[3]), "r"(b[0]), "r"(b[1]));
}

__device__ __forceinline__ unsigned pack_bf16(float f0, float f1) {
    unsigned short u0 = __bfloat16_as_ushort(__float2bfloat16(f0));
    unsigned short u1 = __bfloat16_as_ushort(__float2bfloat16(f1));
    return (unsigned)u0 | ((unsigned)u1 << 16);
}

__device__ __forceinline__ float bf16_res(float v) {   // v - bf16(v)
    return v - __bfloat162float(__float2bfloat16(v));
}

// Scratch (allocation-free rule: __device__ globals)
__device__ float g_xg[(size_t)BB * TT * GG];  // [B*T, 3H] input-side pre-acts (includes b_ih)
__device__ float g_hT[BB * HH];               // final hidden state

extern __shared__ __align__(16) char g_dsmem[];

#define HGS 388                  // padded f32 row stride (frag-store tiles)

// ---------------------------------------------------------------------------
// Kernel A: xg = x @ W_ih^T + b_ih — unchanged from R14 pass (339 us).
// 296 blocks x 256 threads, 2 blocks/SM co-residency.
// ---------------------------------------------------------------------------
#define XNT (BB * TT / 16)       // 32768 tiles
#define X_THREADS 256
#define X_BLOCKS 296
#define WPAD 72                  // padded bf16 K-stride

#define X_OFF_WLO 0
#define X_SZ_WLO  (GG * WPAD * 2)           // 55296
#define X_OFF_XF  (X_OFF_WLO + X_SZ_WLO)
#define X_SZ_XF   (2 * 16 * FF * 4)         // 8192
#define X_OFF_XHI (X_OFF_XF + X_SZ_XF)
#define X_SZ_XB   (2 * 16 * WPAD * 2)       // 4608
#define X_OFF_XLO (X_OFF_XHI + X_SZ_XB)
#define X_OFF_HG  (X_OFF_XLO + X_SZ_XB)
#define X_SZ_HG   (16 * HGS * 4)            // 24832
#define X_OFF_BS  (X_OFF_HG + X_SZ_HG)
#define X_SZ_BS   (GG * 4)
#define X_SMEM    (X_OFF_BS + X_SZ_BS)      // 99072 B (x2 blocks <= 228KB/SM)

__global__ __launch_bounds__(X_THREADS, 2) void xg_mma_kernel(
    const float* __restrict__ x,
    const float* __restrict__ W_ih,
    const float* __restrict__ b_ih)
{
    __nv_bfloat16* Wlo = (__nv_bfloat16*)(g_dsmem + X_OFF_WLO);
    float* Xf = (float*)(g_dsmem + X_OFF_XF);
    __nv_bfloat16* Xhi = (__nv_bfloat16*)(g_dsmem + X_OFF_XHI);
    __nv_bfloat16* Xlo = (__nv_bfloat16*)(g_dsmem + X_OFF_XLO);
    float* HG = (float*)(g_dsmem + X_OFF_HG);
    float* BS = (float*)(g_dsmem + X_OFF_BS);

    const int tid = threadIdx.x;
    const int warp = tid >> 5;
    const int lane = tid & 31;
    const int gid = lane >> 2;
    const int tig = lane & 3;
    const int n0 = warp * 48;

    for (int i = tid; i < GG * FF; i += X_THREADS) {
        int n = i >> 6, k = i & 63;
        float w = W_ih[i];
        Wlo[n * WPAD + k] = __float2bfloat16(bf16_res(w));
    }
    for (int i = tid; i < GG; i += X_THREADS) BS[i] = b_ih[i];

    unsigned bhi[6][4][2];
#pragma unroll
    for (int nt = 0; nt < 6; nt++)
#pragma unroll
        for (int kt = 0; kt < 4; kt++) {
            const float* wr = W_ih + (size_t)(n0 + nt * 8 + gid) * FF + kt * 16 + 2 * tig;
            bhi[nt][kt][0] = pack_bf16(wr[0], wr[1]);
            bhi[nt][kt][1] = pack_bf16(wr[8], wr[9]);
        }

    const unsigned xf_base = (unsigned)__cvta_generic_to_shared(Xf);
    auto stage = [&](int tile, int buf) {
        if (tile < XNT)
            cp_async16(xf_base + (unsigned)buf * 4096u + (unsigned)tid * 16u,
                       (const char*)x + (size_t)tile * 4096 + (size_t)tid * 16);
        cp_commit();
    };

    stage(blockIdx.x, 0);
    cp_wait_all();
    __syncthreads();

    int it = 0;
    for (int tile = blockIdx.x; tile < XNT; tile += gridDim.x, it++) {
        const int buf = it & 1;
        stage(tile + gridDim.x, buf ^ 1);

        for (int i = tid; i < 16 * FF; i += X_THREADS) {
            int r = i >> 6, c = i & 63;
            float v = Xf[buf * 1024 + i];
            __nv_bfloat16 hi = __float2bfloat16(v);
            Xhi[buf * 16 * WPAD + r * WPAD + c] = hi;
            Xlo[buf * 16 * WPAD + r * WPAD + c] =
                __float2bfloat16(v - __bfloat162float(hi));
        }
        __syncthreads();

        float acc[6][4];
#pragma unroll
        for (int nt = 0; nt < 6; nt++)
#pragma unroll
            for (int i = 0; i < 4; i++) acc[nt][i] = 0.f;

        const __nv_bfloat16* XH = Xhi + buf * 16 * WPAD;
        const __nv_bfloat16* XL = Xlo + buf * 16 * WPAD;
#pragma unroll
        for (int kt = 0; kt < 4; kt++) {
            const int col = kt * 16 + 2 * tig;
            unsigned ah[4], al[4];
            ah[0] = *(const unsigned*)(XH + gid * WPAD + col);
            ah[1] = *(const unsigned*)(XH + (gid + 8) * WPAD + col);
            ah[2] = *(const unsigned*)(XH + gid * WPAD + col + 8);
            ah[3] = *(const unsigned*)(XH + (gid + 8) * WPAD + col + 8);
            al[0] = *(const unsigned*)(XL + gid * WPAD + col);
            al[1] = *(const unsigned*)(XL + (gid + 8) * WPAD + col);
            al[2] = *(const unsigned*)(XL + gid * WPAD + col + 8);
            al[3] = *(const unsigned*)(XL + (gid + 8) * WPAD + col + 8);
#pragma unroll
            for (int nt = 0; nt < 6; nt++) {
                mma_bf16(acc[nt], ah, bhi[nt][kt]);
                mma_bf16(acc[nt], al, bhi[nt][kt]);
                unsigned bl[2];
                const __nv_bfloat16* wl = Wlo + (size_t)(n0 + nt * 8 + gid) * WPAD + col;
                bl[0] = *(const unsigned*)wl;
                bl[1] = *(const unsigned*)(wl + 8);
                mma_bf16(acc[nt], ah, bl);
            }
        }

#pragma unroll
        for (int nt = 0; nt < 6; nt++) {
            const int ccol = n0 + nt * 8 + 2 * tig;
            *(float2*)(HG + gid * HGS + ccol) = make_float2(acc[nt][0], acc[nt][1]);
            *(float2*)(HG + (gid + 8) * HGS + ccol) = make_float2(acc[nt][2], acc[nt][3]);
        }
        __syncthreads();

        {
            float* dst = g_xg + (size_t)tile * 16 * GG;
#pragma unroll
            for (int p = 0; p < 6; p++) {
                int f = tid + p * X_THREADS;
                int col = (f * 4) % GG;
                int row = (f * 4) / GG;
                float4 v = *(const float4*)(HG + row * HGS + col);
                float4 b = *(const float4*)(BS + col);
                v.x += b.x; v.y += b.y; v.z += b.z; v.w += b.w;
                *(float4*)(dst + (size_t)f * 4) = v;
            }
        }
        cp_wait_all();
        __syncthreads();
    }
}

// ---------------------------------------------------------------------------
// Kernel B v3: phase-pipelined GRU. 32 blocks x 32 batch rows, 512 threads.
// Rows split into 2 independent groups of 16, phase-shifted by half a step:
// each phase runs MMA(group g1) interleaved with gate(group g2) so tensor+LDS
// overlap MUFU. One barrier per phase = 2 per step. xg read directly from
// gmem, prefetched into registers at phase start (hidden behind MMA region).
// ---------------------------------------------------------------------------
#define GMT 32                   // batch rows per block (2 groups of 16)
#define G_BLOCKS (BB / GMT)      // 32
#define G_THREADS 512            // 16 warps
#define NSLICE 24                // gate cols per warp
#define HP 136                   // padded bf16 row stride (h, W_lo)

#define OFF_WLO  0
#define SZ_WLO   (GG * HP * 2)             // 104448
#define SZ_HB    (16 * HP * 2)             // 4352
#define OFF_HHI0 (OFF_WLO + SZ_WLO)
#define OFF_HLO0 (OFF_HHI0 + SZ_HB)
#define OFF_HHI1 (OFF_HLO0 + SZ_HB)
#define OFF_HLO1 (OFF_HHI1 + SZ_HB)
#define SZ_HF    (16 * HH * 4)             // 8192
#define OFF_HF0  (OFF_HLO1 + SZ_HB)
#define OFF_HF1  (OFF_HF0 + SZ_HF)
#define SZ_HG    (16 * HGS * 4)            // 24832
#define OFF_HG0  (OFF_HF1 + SZ_HF)
#define OFF_HG1  (OFF_HG0 + SZ_HG)
#define OFF_BS   (OFF_HG1 + SZ_HG)
#define SZ_BS    (GG * 4)
#define G_SMEM   (OFF_BS + SZ_BS)          // 189440 B

__global__ __launch_bounds__(G_THREADS, 1) void gru_pipe_kernel(
    const float* __restrict__ W_hh,
    const float* __restrict__ b_hh)
{
    __nv_bfloat16* Wlo  = (__nv_bfloat16*)(g_dsmem + OFF_WLO);
    __nv_bfloat16* Hhi_g[2] = { (__nv_bfloat16*)(g_dsmem + OFF_HHI0),
                                (__nv_bfloat16*)(g_dsmem + OFF_HHI1) };
    __nv_bfloat16* Hlo_g[2] = { (__nv_bfloat16*)(g_dsmem + OFF_HLO0),
                                (__nv_bfloat16*)(g_dsmem + OFF_HLO1) };
    float* Hf_g[2] = { (float*)(g_dsmem + OFF_HF0), (float*)(g_dsmem + OFF_HF1) };
    float* HG_g[2] = { (float*)(g_dsmem + OFF_HG0), (float*)(g_dsmem + OFF_HG1) };
    float* BS = (float*)(g_dsmem + OFF_BS);

    const int tid = threadIdx.x;
    const int warp = tid >> 5;
    const int lane = tid & 31;
    const int gid = lane >> 2;
    const int tig = lane & 3;
    const int n0 = warp * NSLICE;
    const int row0 = blockIdx.x * GMT;

    // one-time init: W_lo split, biases, h = 0
    for (int i = tid; i < GG * HH; i += G_THREADS) {
        int n = i >> 7, k = i & 127;
        float w = W_hh[i];
        Wlo[n * HP + k] = __float2bfloat16(bf16_res(w));
    }
    for (int i = tid; i < GG; i += G_THREADS) BS[i] = b_hh[i];
    {
        __nv_bfloat16 z = __float2bfloat16(0.f);
        for (int i = tid; i < 16 * HP; i += G_THREADS) {
            Hhi_g[0][i] = z; Hlo_g[0][i] = z; Hhi_g[1][i] = z; Hlo_g[1][i] = z;
        }
        for (int i = tid; i < 16 * HH; i += G_THREADS) { Hf_g[0][i] = 0.f; Hf_g[1][i] = 0.f; }
    }

    // stationary W_hi fragments (3 n-tiles x 8 k-tiles)
    unsigned bhi[3][8][2];
#pragma unroll
    for (int nt = 0; nt < 3; nt++)
#pragma unroll
        for (int kt = 0; kt < 8; kt++) {
            const float* wr = W_hh + (size_t)(n0 + nt * 8 + gid) * HH + kt * 16 + 2 * tig;
            bhi[nt][kt][0] = pack_bf16(wr[0], wr[1]);
            bhi[nt][kt][1] = pack_bf16(wr[8], wr[9]);
        }
    __syncthreads();

    const int jj = tid & 127;                // gate column
    const int rb = tid >> 7;                 // gate row base 0..3

    // Phase loop: phase p runs MMA(g1 = p&1, t1 = p>>1) interleaved with
    // gate(g2 = g1^1, t2 = (p-1)>>1). Groups advance on opposite parities.
    for (int p = 0; p <= 2 * TT; p++) {
        const int g1 = p & 1;
        const int g2 = g1 ^ 1;
        const bool do_mma = (p < 2 * TT);
        const bool do_gate = (p >= 1);
        const int t2 = (p - 1) >> 1;

        // 1) prefetch gate group's xg into registers (consumed after MMA region)
        float xr[4], xz[4], xn[4];
        if (do_gate) {
#pragma unroll
            for (int q = 0; q < 4; q++) {
                const int r = rb + q * 4;
                const float* base =
                    g_xg + ((size_t)(row0 + g2 * 16 + r) * TT + t2) * GG;
                xr[q] = __ldg(base + jj);
                xz[q] = __ldg(base + 128 + jj);
                xn[q] = __ldg(base + 256 + jj);
            }
        }

        // 2) MMA region: hg[g1] = h[g1] @ W^T (3-product bf16 split)
        if (do_mma) {
            const __nv_bfloat16* HhiX = Hhi_g[g1];
            const __nv_bfloat16* HloX = Hlo_g[g1];
            float* HGX = HG_g[g1];

            float acc[3][4];
#pragma unroll
            for (int nt = 0; nt < 3; nt++)
#pragma unroll
                for (int i = 0; i < 4; i++) acc[nt][i] = 0.f;

#pragma unroll
            for (int kt = 0; kt < 8; kt++) {
                const int col = kt * 16 + 2 * tig;
                unsigned ah[4], al[4];
                ah[0] = *(const unsigned*)(HhiX + gid * HP + col);
                ah[1] = *(const unsigned*)(HhiX + (gid + 8) * HP + col);
                ah[2] = *(const unsigned*)(HhiX + gid * HP + col + 8);
                ah[3] = *(const unsigned*)(HhiX + (gid + 8) * HP + col + 8);
                al[0] = *(const unsigned*)(HloX + gid * HP + col);
                al[1] = *(const unsigned*)(HloX + (gid + 8) * HP + col);
                al[2] = *(const unsigned*)(HloX + gid * HP + col + 8);
                al[3] = *(const unsigned*)(HloX + (gid + 8) * HP + col + 8);
#pragma unroll
                for (int nt = 0; nt < 3; nt++) {
                    mma_bf16(acc[nt], ah, bhi[nt][kt]);   // hi * hi
                    mma_bf16(acc[nt], al, bhi[nt][kt]);   // lo * hi
                    unsigned bl[2];
                    const __nv_bfloat16* wl = Wlo + (size_t)(n0 + nt * 8 + gid) * HP + col;
                    bl[0] = *(const unsigned*)wl;
                    bl[1] = *(const unsigned*)(wl + 8);
                    mma_bf16(acc[nt], ah, bl);            // hi * lo
                }
            }

#pragma unroll
            for (int nt = 0; nt < 3; nt++) {
                const int ccol = n0 + nt * 8 + 2 * tig;
                *(float2*)(HGX + gid * HGS + ccol) = make_float2(acc[nt][0], acc[nt][1]);
                *(float2*)(HGX + (gid + 8) * HGS + ccol) = make_float2(acc[nt][2], acc[nt][3]);
            }
        }

        // 3) gate region for group g2 (reads HG[g2] written last phase)
        if (do_gate) {
            const float* HGX = HG_g[g2];
            float* HfX = Hf_g[g2];
            __nv_bfloat16* HhiX = Hhi_g[g2];
            __nv_bfloat16* HloX = Hlo_g[g2];
#pragma unroll
            for (int q = 0; q < 4; q++) {
                const int r = rb + q * 4;
                float pr = HGX[r * HGS + jj] + xr[q] + BS[jj];
                float pz = HGX[r * HGS + 128 + jj] + xz[q] + BS[128 + jj];
                float pn = HGX[r * HGS + 256 + jj] + BS[256 + jj];
                float rr = sigmoid_fast(pr);
                float zz = sigmoid_fast(pz);
                float nn = tanh_fast(xn[q] + rr * pn);
                float h = (1.f - zz) * nn + zz * HfX[r * HH + jj];
                HfX[r * HH + jj] = h;
                __nv_bfloat16 hi = __float2bfloat16(h);
                HhiX[r * HP + jj] = hi;
                HloX[r * HP + jj] = __float2bfloat16(h - __bfloat162float(hi));
            }
        }

        __syncthreads();
    }

    // emit final hidden state (both groups)
    for (int i = tid; i < GMT * HH; i += G_THREADS) {
        int r = i >> 7, j = i & 127;
        int g = r >> 4, rl = r & 15;
        g_hT[(size_t)(row0 + r) * HH + j] = Hf_g[g][rl * HH + j];
    }
}

// ---------------------------------------------------------------------------
// Kernel C: out[b] = W2 . relu(hT[b] @ W1^T + b1) + b2. One warp per row.
// ---------------------------------------------------------------------------
__global__ void head_kernel(
    const float* __restrict__ W1,
    const float* __restrict__ b1,
    const float* __restrict__ W2,
    const float* __restrict__ b2,
    float* __restrict__ out)
{
    const int b = blockIdx.x;
    const int j = threadIdx.x;
    const float* h = g_hT + (size_t)b * HH;

    float acc = 0.f;
#pragma unroll
    for (int k = 0; k < HH; k++)
        acc = fmaf(h[k], W1[j * HH + k], acc);

    float hid = fmaxf(acc + b1[j], 0.f);
    float v = hid * W2[j];
#pragma unroll
    for (int off = 16; off; off >>= 1)
        v += __shfl_xor_sync(0xffffffffu, v, off);
    if (j == 0) out[b] = v + b2[0];
}

// ---------------------------------------------------------------------------
extern "C" void kernel_launch(void* const* d_in, const int* in_sizes, int n_in,
                              void* d_out, int out_size)
{
    const float* x    = (const float*)d_in[0];
    const float* W_ih = (const float*)d_in[1];
    const float* W_hh = (const float*)d_in[2];
    const float* b_ih = (const float*)d_in[3];
    const float* b_hh = (const float*)d_in[4];
    const float* W1   = (const float*)d_in[5];
    const float* b1   = (const float*)d_in[6];
    const float* W2   = (const float*)d_in[7];
    const float* b2   = (const float*)d_in[8];
    float* out        = (float*)d_out;

    cudaFuncSetAttribute(xg_mma_kernel,
                         cudaFuncAttributeMaxDynamicSharedMemorySize, X_SMEM);
    cudaFuncSetAttribute(gru_pipe_kernel,
                         cudaFuncAttributeMaxDynamicSharedMemorySize, G_SMEM);

    xg_mma_kernel<<<X_BLOCKS, X_THREADS, X_SMEM>>>(x, W_ih, b_ih);
    gru_pipe_kernel<<<G_BLOCKS, G_THREADS, G_SMEM>>>(W_hh, b_hh);
    head_kernel<<<BB, 32>>>(W1, b1, W2, b2, out);
}